// round 7
// baseline (speedup 1.0000x reference)
#include <cuda_runtime.h>

// Problem constants (B=128, T=512, X=64, H=256)
#define B_     128
#define T_     512
#define X_     64
#define H_     256
#define KK     320
#define NGROUP 16
#define GSIZE  8
#define GRID_  (NGROUP * GSIZE)   // 128
#define NTHR   256                // 8 warps, 2/SMSP balanced

// ---- smem layout (float offsets) ----
#define OFF_WO   0        // float [256][8]   (2048)  W_out slice [kk][xl]
#define OFF_HID  2048     // float [320][8]   (2560)  gated GEMM input, kk-major
#define OFF_SP   4608     // float [256][8]   (2048)  h_prev + skip_p
#define OFF_RED  6656     // u64   [256][17]  (8704 floats) gate partials
#define OFF_REDP 15360    // u64   [256]      (512 floats)  projection partials
#define OFF_M0   15872    // float[512]
#define OFF_M1   16384    // float[512]
#define SMEM_FLOATS 16896
#define SMEM_BYTES  (SMEM_FLOATS * 4)   // 67584 B

// GRU hidden history buf[t][b][k] (write-once slots per launch)
__device__ float    g_buf[(size_t)T_ * B_ * H_];
__device__ unsigned g_bars[NGROUP * 32];

__global__ void init_kernel() {
    if (threadIdx.x < NGROUP * 32) g_bars[threadIdx.x] = 0u;
}

// ---- packed f32x2 helpers ----
__device__ __forceinline__ unsigned long long pk2(float a, float b) {
    unsigned long long r;
    asm("mov.b64 %0, {%1, %2};" : "=l"(r) : "f"(a), "f"(b));
    return r;
}
__device__ __forceinline__ void fma2(unsigned long long& d,
                                     unsigned long long a, unsigned long long b) {
    asm("fma.rn.f32x2 %0, %1, %2, %0;" : "+l"(d) : "l"(a), "l"(b));
}
__device__ __forceinline__ unsigned long long add2(unsigned long long a,
                                                   unsigned long long b) {
    unsigned long long d;
    asm("add.rn.f32x2 %0, %1, %2;" : "=l"(d) : "l"(a), "l"(b));
    return d;
}
__device__ __forceinline__ float2 up2(unsigned long long v) {
    float2 r;
    asm("mov.b64 {%0, %1}, %2;" : "=f"(r.x), "=f"(r.y) : "l"(v));
    return r;
}

// ---- barrier primitives ----
__device__ __forceinline__ void bar_arrive(unsigned* p) {
    asm volatile("red.release.gpu.add.u32 [%0], %1;" :: "l"(p), "r"(1u) : "memory");
}
__device__ __forceinline__ unsigned bar_ld(unsigned* p) {
    unsigned v;
    asm volatile("ld.acquire.gpu.b32 %0, [%1];" : "=r"(v) : "l"(p) : "memory");
    return v;
}

__device__ __forceinline__ float sig_fast(float x) {
    return 1.0f / (1.0f + __expf(-x));
}
__device__ __forceinline__ float tanh_fast(float x) {
    x = fminf(15.0f, fmaxf(-15.0f, x));
    float e = __expf(-2.0f * x);
    return (1.0f - e) / (1.0f + e);
}

__device__ __forceinline__ void tables(int t, int skip, int& gidx, bool& gz,
                                       int& pidx, bool& pz, bool& late) {
    int pg = (t < skip) ? 2 * t : (t - skip);
    gz = pg < skip; gidx = pg - skip; if (gidx < 0) gidx = 0;
    int pp = (t < skip) ? 2 * t + 1 : (t - skip);
    pz = pp < skip; pidx = pp - skip; if (pidx < 0) pidx = 0;
    late = (!pz) && (pidx >= t);
}

extern __shared__ float smem[];

__global__ void __launch_bounds__(NTHR, 1) decoder_kernel(
    const float* __restrict__ h_enc,
    const float* __restrict__ W_ih,
    const float* __restrict__ W_hh,
    const float* __restrict__ b_ih,
    const float* __restrict__ b_hh,
    const float* __restrict__ W_out,
    const float* __restrict__ b_out,
    const int*   __restrict__ mask0,
    const int*   __restrict__ mask1,
    const int*   __restrict__ skipp,
    float*       __restrict__ out)
{
    const int tid  = threadIdx.x;
    const int cta  = blockIdx.x;
    const int rank = cta & 7;
    const int grp  = cta >> 3;
    const int b0   = grp * 8;
    const int k0   = rank * 32;
    const int skip = skipp ? skipp[0] : 4;
    unsigned* ctr  = &g_bars[grp * 32];
    unsigned  barno = 0;

    float*  Wo  = smem + OFF_WO;
    float*  hid = smem + OFF_HID;
    float*  sP  = smem + OFF_SP;
    float*  red = smem + OFF_RED;
    unsigned long long* redu  = (unsigned long long*)(smem + OFF_RED);
    unsigned long long* redpu = (unsigned long long*)(smem + OFF_REDP);
    float*  m0s = smem + OFF_M0;
    float*  m1s = smem + OFF_M1;
    const unsigned smem_u32 = (unsigned)__cvta_generic_to_shared(smem);

    const int kl = tid & 31;
    const int q  = tid >> 5;                 // warp 0..7
    const int lane = tid & 31;

    // ================= one-time staging =================
    // register-resident gate weights: k-col (k0+kl), contraction segs
    float whr[32], whz[32], whn[32];
    {
        const float* pr = W_hh + (size_t)(k0 + kl) * H_ + q * 32;
        const float* pz = W_hh + (size_t)(k0 + kl + H_) * H_ + q * 32;
        const float* pn = W_hh + (size_t)(k0 + kl + 2 * H_) * H_ + q * 32;
        #pragma unroll
        for (int i = 0; i < 32; ++i) {
            whr[i] = __ldg(pr + i);
            whz[i] = __ldg(pz + i);
            whn[i] = __ldg(pn + i);
        }
    }
    float wxr[8], wxz[8], wxn[8];
    {
        const float* pr = W_ih + (size_t)(k0 + kl) * X_ + q * 8;
        const float* pz = W_ih + (size_t)(k0 + kl + H_) * X_ + q * 8;
        const float* pn = W_ih + (size_t)(k0 + kl + 2 * H_) * X_ + q * 8;
        #pragma unroll
        for (int j = 0; j < 8; ++j) {
            wxr[j] = __ldg(pr + j);
            wxz[j] = __ldg(pz + j);
            wxn[j] = __ldg(pn + j);
        }
    }
    for (int i = tid; i < H_ * 8; i += NTHR) {       // projection slice
        int kk = i >> 3, xl2 = i & 7;
        Wo[i] = W_out[(size_t)(rank * 8 + xl2) * H_ + kk];
    }
    for (int i = tid; i < T_; i += NTHR) {
        m0s[i] = (float)mask0[i];
        m1s[i] = (float)mask1[i];
    }

    float br = 0.f, bz = 0.f, bnh = 0.f, bni = 0.f;
    {
        int k = k0 + kl;
        br  = b_ih[k] + b_hh[k];
        bz  = b_ih[k + H_] + b_hh[k + H_];
        bnh = b_hh[k + 2 * H_];
        bni = b_ih[k + 2 * H_];
    }
    float bo = 0.f;
    if (tid < 32) bo = b_out[rank * 8 + (tid & 7)];

    const unsigned hidh = smem_u32 + (OFF_HID + q * 32 * 8) * 4;
    const unsigned hidx = smem_u32 + (OFF_HID + (256 + q * 8) * 8) * 4;
    const int xl  = tid & 7;
    const int bl2 = (tid >> 3) & 3;

    __syncthreads();

    float g[8], sp[8];
    #pragma unroll
    for (int j = 0; j < 8; ++j) { g[j] = 0.f; sp[j] = 0.f; }
    bool have = true;

    for (int t = 0; t < T_; ++t) {
        int gidx, pidx; bool gz, pz, late;
        tables(t, skip, gidx, gz, pidx, pz, late);
        const bool usesp = (!pz) && (!late);

        // ---- fix-up sub-phase: previous step was "late" -> compute out(t-1) ----
        if (t > 0) {
            int g2, p2; bool z2, q2, l2;
            tables(t - 1, skip, g2, z2, p2, q2, l2);
            if (l2) {
                const float* a = (t >= 2) ? (g_buf + (size_t)(t - 2) * B_ * H_) : h_enc;
                const float* b = g_buf + (size_t)p2 * B_ * H_;
                int kk = tid;
                float v[8];
                #pragma unroll
                for (int j = 0; j < 8; ++j) {
                    float av = (t >= 2) ? __ldcg(a + (size_t)(b0 + j) * H_ + kk)
                                        : __ldg(a + (size_t)(b0 + j) * H_ + kk);
                    v[j] = av + __ldcg(b + (size_t)(b0 + j) * H_ + kk);
                }
                *(float4*)(sP + kk * 8)     = make_float4(v[0], v[1], v[2], v[3]);
                *(float4*)(sP + kk * 8 + 4) = make_float4(v[4], v[5], v[6], v[7]);
                __syncthreads();
                {
                    unsigned long long acc = 0;
                    #pragma unroll 8
                    for (int i = 0; i < 32; ++i) {
                        int kk2 = q * 32 + i;
                        unsigned long long s2 =
                            *(const unsigned long long*)(sP + kk2 * 8 + 2 * bl2);
                        float w = Wo[kk2 * 8 + xl];
                        fma2(acc, pk2(w, w), s2);
                    }
                    redpu[tid] = acc;
                }
                __syncthreads();
                if (tid < 32) {
                    unsigned long long a2 = 0;
                    #pragma unroll
                    for (int qq = 0; qq < 8; ++qq) a2 = add2(a2, redpu[qq * 32 + tid]);
                    float2 f = up2(a2);
                    f.x += bo; f.y += bo;
                    int xg = rank * 8 + (tid & 7);
                    int bb = (tid >> 3) & 3;
                    __stcg(out + ((size_t)(b0 + 2 * bb) * T_ + (t - 1)) * X_ + xg, f.x);
                    __stcg(out + ((size_t)(b0 + 2 * bb + 1) * T_ + (t - 1)) * X_ + xg, f.y);
                }
                __syncthreads();
                if (tid == 0) bar_arrive(ctr);
                ++barno;
                if (lane == 0) {
                    unsigned tgt = barno * GSIZE;
                    while (bar_ld(ctr) < tgt) {}
                }
                __syncwarp();
            }
        }

        // ---- staging: gated hidden + projection input + x ----
        {
            float m0 = m0s[t], m1 = m1s[t];
            int kk = tid;
            if (!have) {
                #pragma unroll
                for (int j = 0; j < 8; ++j) {
                    g[j]  = gz ? 0.f
                               : __ldcg(g_buf + ((size_t)gidx * B_ + b0 + j) * H_ + kk);
                    sp[j] = usesp
                               ? ((pidx == gidx && !gz) ? g[j]
                                  : __ldcg(g_buf + ((size_t)pidx * B_ + b0 + j) * H_ + kk))
                               : 0.f;
                }
            }
            const float* hsrc = t ? (g_buf + (size_t)(t - 1) * B_ * H_) : h_enc;
            float hv[8];
            #pragma unroll
            for (int j = 0; j < 8; ++j)
                hv[j] = t ? __ldcg(hsrc + (size_t)(b0 + j) * H_ + kk)
                          : __ldg(hsrc + (size_t)(b0 + j) * H_ + kk);
            float xv[8];
            if (tid < 64) {
                #pragma unroll
                for (int j = 0; j < 8; ++j)
                    xv[j] = t ? __ldcg(out + ((size_t)(b0 + j) * T_ + (t - 1)) * X_ + tid)
                              : 0.f;
            }
            *(float4*)(hid + kk * 8) =
                make_float4(hv[0] * m0 + g[0] * m1, hv[1] * m0 + g[1] * m1,
                            hv[2] * m0 + g[2] * m1, hv[3] * m0 + g[3] * m1);
            *(float4*)(hid + kk * 8 + 4) =
                make_float4(hv[4] * m0 + g[4] * m1, hv[5] * m0 + g[5] * m1,
                            hv[6] * m0 + g[6] * m1, hv[7] * m0 + g[7] * m1);
            *(float4*)(sP + kk * 8) =
                make_float4(hv[0] + sp[0], hv[1] + sp[1], hv[2] + sp[2], hv[3] + sp[3]);
            *(float4*)(sP + kk * 8 + 4) =
                make_float4(hv[4] + sp[4], hv[5] + sp[5], hv[6] + sp[6], hv[7] + sp[7]);
            if (tid < 64) {
                *(float4*)(hid + (256 + tid) * 8) =
                    make_float4(xv[0], xv[1], xv[2], xv[3]);
                *(float4*)(hid + (256 + tid) * 8 + 4) =
                    make_float4(xv[4], xv[5], xv[6], xv[7]);
            }
        }
        __syncthreads();

        // ---- gate GEMM: register-resident weights ----
        {
            unsigned long long ar[4], az[4], anh[4], ani[4];
            #pragma unroll
            for (int p = 0; p < 4; ++p) { ar[p] = 0; az[p] = 0; anh[p] = 0; ani[p] = 0; }
            #pragma unroll
            for (int i = 0; i < 32; ++i) {
                unsigned long long wr2 = pk2(whr[i], whr[i]);
                unsigned long long wz2 = pk2(whz[i], whz[i]);
                unsigned long long wn2 = pk2(whn[i], whn[i]);
                unsigned long long h01, h23, h45, h67;
                asm("ld.shared.v2.u64 {%0, %1}, [%2];"
                    : "=l"(h01), "=l"(h23) : "r"(hidh + i * 32));
                asm("ld.shared.v2.u64 {%0, %1}, [%2];"
                    : "=l"(h45), "=l"(h67) : "r"(hidh + i * 32 + 16));
                fma2(ar[0], wr2, h01); fma2(ar[1], wr2, h23);
                fma2(ar[2], wr2, h45); fma2(ar[3], wr2, h67);
                fma2(az[0], wz2, h01); fma2(az[1], wz2, h23);
                fma2(az[2], wz2, h45); fma2(az[3], wz2, h67);
                fma2(anh[0], wn2, h01); fma2(anh[1], wn2, h23);
                fma2(anh[2], wn2, h45); fma2(anh[3], wn2, h67);
            }
            #pragma unroll
            for (int j = 0; j < 8; ++j) {
                unsigned long long wr2 = pk2(wxr[j], wxr[j]);
                unsigned long long wz2 = pk2(wxz[j], wxz[j]);
                unsigned long long wn2 = pk2(wxn[j], wxn[j]);
                unsigned long long h01, h23, h45, h67;
                asm("ld.shared.v2.u64 {%0, %1}, [%2];"
                    : "=l"(h01), "=l"(h23) : "r"(hidx + j * 32));
                asm("ld.shared.v2.u64 {%0, %1}, [%2];"
                    : "=l"(h45), "=l"(h67) : "r"(hidx + j * 32 + 16));
                fma2(ar[0], wr2, h01); fma2(ar[1], wr2, h23);
                fma2(ar[2], wr2, h45); fma2(ar[3], wr2, h67);
                fma2(az[0], wz2, h01); fma2(az[1], wz2, h23);
                fma2(az[2], wz2, h45); fma2(az[3], wz2, h67);
                fma2(ani[0], wn2, h01); fma2(ani[1], wn2, h23);
                fma2(ani[2], wn2, h45); fma2(ani[3], wn2, h67);
            }
            unsigned long long* rp = redu + (q * 32 + kl) * 17;
            #pragma unroll
            for (int p = 0; p < 4; ++p) {
                rp[p * 4 + 0] = ar[p];
                rp[p * 4 + 1] = az[p];
                rp[p * 4 + 2] = anh[p];
                rp[p * 4 + 3] = ani[p];
            }
        }

        // ---- projection partials (reads sP, stable since staging) ----
        if (!late) {
            unsigned long long acc = 0;
            #pragma unroll 8
            for (int i = 0; i < 32; ++i) {
                int kk2 = q * 32 + i;
                unsigned long long s2 =
                    *(const unsigned long long*)(sP + kk2 * 8 + 2 * bl2);
                float w = Wo[kk2 * 8 + xl];
                fma2(acc, pk2(w, w), s2);
            }
            redpu[tid] = acc;
        }
        __syncthreads();

        // ---- finalize h(t) + projection reduce ----
        {
            int bl = tid >> 5, klf = tid & 31;
            int p = bl >> 1, half = bl & 1;
            float sr = 0.f, sz = 0.f, snh = 0.f, sni = 0.f;
            #pragma unroll
            for (int qq = 0; qq < 8; ++qq) {
                const float* pr = red + (qq * 32 + klf) * 34 + p * 8 + half;
                sr  += pr[0];
                sz  += pr[2];
                snh += pr[4];
                sni += pr[6];
            }
            float r  = sig_fast(sr + br);
            float z  = sig_fast(sz + bz);
            float n  = tanh_fast(sni + bni + r * (snh + bnh));
            float hv = hid[(k0 + klf) * 8 + bl];
            float hn = (1.0f - z) * n + z * hv;
            __stcg(g_buf + ((size_t)t * B_ + (b0 + bl)) * H_ + (k0 + klf), hn);
        }
        if (!late && tid < 32) {
            unsigned long long a2 = 0;
            #pragma unroll
            for (int qq = 0; qq < 8; ++qq) a2 = add2(a2, redpu[qq * 32 + tid]);
            float2 f = up2(a2);
            f.x += bo; f.y += bo;
            int xg = rank * 8 + (tid & 7);
            int bb = (tid >> 3) & 3;
            __stcg(out + ((size_t)(b0 + 2 * bb) * T_ + t) * X_ + xg, f.x);
            __stcg(out + ((size_t)(b0 + 2 * bb + 1) * T_ + t) * X_ + xg, f.y);
        }

        // ---- group barrier: arrive, prefetch in window, warp-autonomous poll ----
        __syncthreads();
        if (tid == 0) bar_arrive(ctr);
        ++barno;

        have = false;
        if (t + 1 < T_) {
            int ngidx, npidx; bool ngz, npz, nlate;
            tables(t + 1, skip, ngidx, ngz, npidx, npz, nlate);
            bool nuse = (!npz) && (!nlate);
            bool safe = (ngz || ngidx < t) && (!nuse || npidx < t);
            if (safe) {
                int kk = tid;
                if (!ngz && nuse && ngidx == npidx) {
                    #pragma unroll
                    for (int j = 0; j < 8; ++j) {
                        g[j] = __ldcg(g_buf + ((size_t)ngidx * B_ + b0 + j) * H_ + kk);
                        sp[j] = g[j];
                    }
                } else {
                    #pragma unroll
                    for (int j = 0; j < 8; ++j) {
                        g[j]  = ngz ? 0.f
                                    : __ldcg(g_buf + ((size_t)ngidx * B_ + b0 + j) * H_ + kk);
                        sp[j] = nuse
                                    ? __ldcg(g_buf + ((size_t)npidx * B_ + b0 + j) * H_ + kk)
                                    : 0.f;
                    }
                }
                have = true;
            }
        }

        if (lane == 0) {
            unsigned tgt = barno * GSIZE;
            while (bar_ld(ctr) < tgt) {}
        }
        __syncwarp();
    }
}

extern "C" void kernel_launch(void* const* d_in, const int* in_sizes, int n_in,
                              void* d_out, int out_size) {
    const float* h_enc = (const float*)d_in[1];
    const float* W_ih  = (const float*)d_in[2];
    const float* W_hh  = (const float*)d_in[3];
    const float* b_ih  = (const float*)d_in[4];
    const float* b_hh  = (const float*)d_in[5];
    const float* W_out = (const float*)d_in[6];
    const float* b_out = (const float*)d_in[7];
    const int*   mask0 = (const int*)d_in[8];
    const int*   mask1 = (const int*)d_in[9];
    const int*   skipp = (n_in > 10) ? (const int*)d_in[10] : (const int*)0;

    cudaFuncSetAttribute(decoder_kernel,
                         cudaFuncAttributeMaxDynamicSharedMemorySize, SMEM_BYTES);
    init_kernel<<<1, NGROUP * 32>>>();
    decoder_kernel<<<GRID_, NTHR, SMEM_BYTES>>>(
        h_enc, W_ih, W_hh, b_ih, b_hh, W_out, b_out, mask0, mask1, skipp,
        (float*)d_out);
}